// round 3
// baseline (speedup 1.0000x reference)
#include <cuda_runtime.h>

#define MAXN 100000
#define MAXE 1600000
#define C 64

// ---------------- scratch (static device globals; no allocation) ------------
__device__ int   g_count[MAXN];
__device__ int   g_incl[MAXN + 1024];
__device__ int   g_bsum[128];
__device__ int   g_bpref[128];
__device__ int   g_off[MAXN + 1];
__device__ int   g_cur[MAXN];
__device__ int   g_csr[MAXE];
__device__ float g_dinv[MAXN];
__device__ float g_agg[MAXN * C];
__device__ float g_h1[MAXN * C];
__device__ float g_h2[MAXN * C];

// ---------------- CSR build -------------------------------------------------
__global__ void k_zero(int n) {
    int i = blockIdx.x * blockDim.x + threadIdx.x;
    if (i < n) g_count[i] = 0;
}

__global__ void k_hist(const int* __restrict__ row, int e) {
    int i = blockIdx.x * blockDim.x + threadIdx.x;
    if (i < e) atomicAdd(&g_count[row[i]], 1);
}

// block-level inclusive scan (1024 elems/block)
__global__ void k_scan1(int n) {
    __shared__ int sh[1024];
    int t = threadIdx.x;
    int i = blockIdx.x * 1024 + t;
    sh[t] = (i < n) ? g_count[i] : 0;
    __syncthreads();
    #pragma unroll
    for (int off = 1; off < 1024; off <<= 1) {
        int add = (t >= off) ? sh[t - off] : 0;
        __syncthreads();
        sh[t] += add;
        __syncthreads();
    }
    g_incl[i] = sh[t];
    if (t == 1023) g_bsum[blockIdx.x] = sh[1023];
}

__global__ void k_scan2(int nblk) {
    int run = 0;
    for (int b = 0; b < nblk; b++) { g_bpref[b] = run; run += g_bsum[b]; }
}

__global__ void k_scan3(int n, int e) {
    int i = blockIdx.x * blockDim.x + threadIdx.x;
    if (i < n) {
        int cnt = g_count[i];
        int off = g_incl[i] - cnt + g_bpref[i >> 10];
        g_off[i]  = off;
        g_cur[i]  = off;
        g_dinv[i] = 1.0f / (float)(cnt > 1 ? cnt : 1);
    }
    if (i == 0) g_off[n] = e;
}

__global__ void k_fill(const int* __restrict__ row, const int* __restrict__ col, int e) {
    int i = blockIdx.x * blockDim.x + threadIdx.x;
    if (i < e) {
        int p = atomicAdd(&g_cur[row[i]], 1);
        g_csr[p] = col[i];
    }
}

// ---------------- mean aggregation: one warp per destination node -----------
// srcSel: 0 -> external X, 1 -> g_h1, 2 -> g_h2.  Output always g_agg.
__global__ void k_agg(const float* __restrict__ Xin, int srcSel, int n) {
    int w    = (blockIdx.x * blockDim.x + threadIdx.x) >> 5;
    int lane = threadIdx.x & 31;
    if (w >= n) return;
    const float* __restrict__ src = (srcSel == 0) ? Xin : (srcSel == 1 ? g_h1 : g_h2);
    int s = g_off[w], e = g_off[w + 1];
    float ax = 0.f, ay = 0.f;
    int j = s;
    int l2 = lane << 1;
    for (; j + 3 < e; j += 4) {
        int c0 = g_csr[j], c1 = g_csr[j + 1], c2 = g_csr[j + 2], c3 = g_csr[j + 3];
        float2 v0 = *(const float2*)(src + c0 * C + l2);
        float2 v1 = *(const float2*)(src + c1 * C + l2);
        float2 v2 = *(const float2*)(src + c2 * C + l2);
        float2 v3 = *(const float2*)(src + c3 * C + l2);
        ax += (v0.x + v1.x) + (v2.x + v3.x);
        ay += (v0.y + v1.y) + (v2.y + v3.y);
    }
    for (; j < e; j++) {
        int c = g_csr[j];
        float2 v = *(const float2*)(src + c * C + l2);
        ax += v.x; ay += v.y;
    }
    float d = g_dinv[w];
    *(float2*)(g_agg + w * C + l2) = make_float2(ax * d, ay * d);
}

// ---------------- GEMM: OUT[n,64] = act( concat(X, AGG)[n,128] @ W^T + b ) --
// Block tile: 128 nodes x 64 cols, k chunked by 32. Thread tile 8x4.
#define NT  128
#define KC  32
#define NTP 132   // padded (16B-multiple rows -> LDS.128 aligned)
#define WTP 68

__global__ __launch_bounds__(256) void k_gemm(
    const float* __restrict__ Xin, int srcSel,
    const float* __restrict__ W, const float* __restrict__ B,
    int dstSel, int n, int do_relu)
{
    __shared__ float Hs[KC][NTP];
    __shared__ float Ws[KC][WTP];

    const float* __restrict__ Xs = (srcSel == 0) ? Xin : (srcSel == 1 ? g_h1 : g_h2);
    float* __restrict__ OUT = (dstSel == 1) ? g_h1 : g_h2;

    int t  = threadIdx.x;
    int nb = blockIdx.x * NT;
    int tx = t & 15;      // node-group (16 groups x 8 nodes)
    int ty = t >> 4;      // col-group  (16 groups x 4 cols)

    float acc[8][4];
    #pragma unroll
    for (int i = 0; i < 8; i++)
        #pragma unroll
        for (int j = 0; j < 4; j++) acc[i][j] = 0.f;

    int nl    = t >> 1;          // local node for H staging (2 threads/row)
    int half  = t & 1;
    int nglob = nb + nl;
    int colw  = t >> 2;          // W staging: col, quarter
    int q     = t & 3;

    for (int c = 0; c < 4; c++) {
        const float* src = (c < 2) ? Xs : g_agg;
        int koff = (c & 1) * 32;     // column offset within the 64-wide source
        int kb   = c * 32;           // global k base (for W)

        // stage H chunk transposed: Hs[kk][node]
        #pragma unroll
        for (int i = 0; i < 4; i++) {
            float4 v = make_float4(0.f, 0.f, 0.f, 0.f);
            if (nglob < n)
                v = *(const float4*)(src + nglob * C + koff + half * 16 + i * 4);
            int kk = half * 16 + i * 4;
            Hs[kk + 0][nl] = v.x;
            Hs[kk + 1][nl] = v.y;
            Hs[kk + 2][nl] = v.z;
            Hs[kk + 3][nl] = v.w;
        }
        // stage W chunk transposed: Ws[kk][col] = W[col][kb+kk]
        #pragma unroll
        for (int i = 0; i < 2; i++) {
            float4 wv = *(const float4*)(W + colw * 128 + kb + q * 8 + i * 4);
            int kk = q * 8 + i * 4;
            Ws[kk + 0][colw] = wv.x;
            Ws[kk + 1][colw] = wv.y;
            Ws[kk + 2][colw] = wv.z;
            Ws[kk + 3][colw] = wv.w;
        }
        __syncthreads();

        #pragma unroll 4
        for (int kk = 0; kk < KC; kk++) {
            float4 a0 = *(const float4*)&Hs[kk][tx * 8];
            float4 a1 = *(const float4*)&Hs[kk][tx * 8 + 4];
            float4 bv = *(const float4*)&Ws[kk][ty * 4];
            float a[8] = {a0.x, a0.y, a0.z, a0.w, a1.x, a1.y, a1.z, a1.w};
            float bb[4] = {bv.x, bv.y, bv.z, bv.w};
            #pragma unroll
            for (int i = 0; i < 8; i++)
                #pragma unroll
                for (int j = 0; j < 4; j++)
                    acc[i][j] += a[i] * bb[j];
        }
        __syncthreads();
    }

    float4 bv = *(const float4*)(B + ty * 4);
    #pragma unroll
    for (int i = 0; i < 8; i++) {
        int ng = nb + tx * 8 + i;
        if (ng < n) {
            float4 o;
            o.x = acc[i][0] + bv.x;
            o.y = acc[i][1] + bv.y;
            o.z = acc[i][2] + bv.z;
            o.w = acc[i][3] + bv.w;
            if (do_relu) {
                o.x = fmaxf(o.x, 0.f); o.y = fmaxf(o.y, 0.f);
                o.z = fmaxf(o.z, 0.f); o.w = fmaxf(o.w, 0.f);
            }
            *(float4*)(OUT + ng * C + ty * 4) = o;
        }
    }
}

// ---------------- layer 3: fused gather + 128-dot + warp reduce -------------
__global__ void k_layer3(const float* __restrict__ W3, const float* __restrict__ B3,
                         float* __restrict__ OUT, int n)
{
    int w    = (blockIdx.x * blockDim.x + threadIdx.x) >> 5;
    int lane = threadIdx.x & 31;
    if (w >= n) return;
    const float* __restrict__ H = g_h2;
    int s = g_off[w], e = g_off[w + 1];
    int l2 = lane << 1;
    float ax = 0.f, ay = 0.f;
    int j = s;
    for (; j + 3 < e; j += 4) {
        int c0 = g_csr[j], c1 = g_csr[j + 1], c2 = g_csr[j + 2], c3 = g_csr[j + 3];
        float2 v0 = *(const float2*)(H + c0 * C + l2);
        float2 v1 = *(const float2*)(H + c1 * C + l2);
        float2 v2 = *(const float2*)(H + c2 * C + l2);
        float2 v3 = *(const float2*)(H + c3 * C + l2);
        ax += (v0.x + v1.x) + (v2.x + v3.x);
        ay += (v0.y + v1.y) + (v2.y + v3.y);
    }
    for (; j < e; j++) {
        int c = g_csr[j];
        float2 v = *(const float2*)(H + c * C + l2);
        ax += v.x; ay += v.y;
    }
    float d = g_dinv[w];
    ax *= d; ay *= d;
    float2 self = *(const float2*)(H + w * C + l2);
    float2 ws   = *(const float2*)(W3 + l2);
    float2 wa   = *(const float2*)(W3 + 64 + l2);
    float p = self.x * ws.x + self.y * ws.y + ax * wa.x + ay * wa.y;
    #pragma unroll
    for (int o = 16; o; o >>= 1) p += __shfl_xor_sync(0xffffffffu, p, o);
    if (lane == 0) OUT[w] = p + B3[0];
}

// ---------------- driver ----------------------------------------------------
extern "C" void kernel_launch(void* const* d_in, const int* in_sizes, int n_in,
                              void* d_out, int out_size)
{
    const float* x  = (const float*)d_in[0];
    const int*   ei = (const int*)  d_in[1];
    const float* W1 = (const float*)d_in[2];
    const float* b1 = (const float*)d_in[3];
    const float* W2 = (const float*)d_in[4];
    const float* b2 = (const float*)d_in[5];
    const float* W3 = (const float*)d_in[6];
    const float* b3 = (const float*)d_in[7];
    float* out = (float*)d_out;

    int n = in_sizes[0] / C;     // 100000
    int e = in_sizes[1] / 2;     // 1600000
    const int* row = ei;
    const int* col = ei + e;

    int nblk = (n + 1023) / 1024;

    // CSR build (reused for all 3 layers)
    k_zero <<<(n + 255) / 256, 256>>>(n);
    k_hist <<<(e + 255) / 256, 256>>>(row, e);
    k_scan1<<<nblk, 1024>>>(n);
    k_scan2<<<1, 1>>>(nblk);
    k_scan3<<<(n + 255) / 256, 256>>>(n, e);
    k_fill <<<(e + 255) / 256, 256>>>(row, col, e);

    int aggBlocks  = (n * 32 + 255) / 256;  // 1 warp per node
    int gemmBlocks = (n + NT - 1) / NT;

    // layer 1: x -> h1
    k_agg <<<aggBlocks, 256>>>(x, 0, n);
    k_gemm<<<gemmBlocks, 256>>>(x, 0, W1, b1, /*dst=*/1, n, /*relu=*/1);
    // layer 2: h1 -> h2
    k_agg <<<aggBlocks, 256>>>(nullptr, 1, n);
    k_gemm<<<gemmBlocks, 256>>>(nullptr, 1, W2, b2, /*dst=*/2, n, /*relu=*/1);
    // layer 3: h2 -> out (fused)
    k_layer3<<<aggBlocks, 256>>>(W3, b3, out, n);
}

// round 4
// speedup vs baseline: 1.0009x; 1.0009x over previous
#include <cuda_runtime.h>

#define MAXN 100000
#define MAXE 1600000
#define C 64

// ---------------- scratch (static device globals; no allocation) ------------
__device__ int   g_count[MAXN];
__device__ int   g_incl[MAXN + 1024];
__device__ int   g_bsum[128];
__device__ int   g_bpref[128];
__device__ int   g_off[MAXN + 1];
__device__ int   g_cur[MAXN];
__device__ int   g_csr[MAXE];
__device__ float g_dinv[MAXN];
__device__ float g_agg[MAXN * C];
__device__ float g_h1[MAXN * C];
__device__ float g_h2[MAXN * C];

// ---------------- CSR build -------------------------------------------------
__global__ void k_zero(int n) {
    int i = blockIdx.x * blockDim.x + threadIdx.x;
    if (i < n) g_count[i] = 0;
}

__global__ void k_hist(const int* __restrict__ row, int e) {
    int i = blockIdx.x * blockDim.x + threadIdx.x;
    if (i < e) atomicAdd(&g_count[row[i]], 1);
}

// block-level inclusive scan (1024 elems/block)
__global__ void k_scan1(int n) {
    __shared__ int sh[1024];
    int t = threadIdx.x;
    int i = blockIdx.x * 1024 + t;
    sh[t] = (i < n) ? g_count[i] : 0;
    __syncthreads();
    #pragma unroll
    for (int off = 1; off < 1024; off <<= 1) {
        int add = (t >= off) ? sh[t - off] : 0;
        __syncthreads();
        sh[t] += add;
        __syncthreads();
    }
    g_incl[i] = sh[t];
    if (t == 1023) g_bsum[blockIdx.x] = sh[1023];
}

__global__ void k_scan2(int nblk) {
    int run = 0;
    for (int b = 0; b < nblk; b++) { g_bpref[b] = run; run += g_bsum[b]; }
}

__global__ void k_scan3(int n, int e) {
    int i = blockIdx.x * blockDim.x + threadIdx.x;
    if (i < n) {
        int cnt = g_count[i];
        int off = g_incl[i] - cnt + g_bpref[i >> 10];
        g_off[i]  = off;
        g_cur[i]  = off;
        g_dinv[i] = 1.0f / (float)(cnt > 1 ? cnt : 1);
    }
    if (i == 0) g_off[n] = e;
}

__global__ void k_fill(const int* __restrict__ row, const int* __restrict__ col, int e) {
    int i = blockIdx.x * blockDim.x + threadIdx.x;
    if (i < e) {
        int p = atomicAdd(&g_cur[row[i]], 1);
        g_csr[p] = col[i];
    }
}

// ---------------- mean aggregation: one warp per destination node -----------
// srcSel: 0 -> external X, 1 -> g_h1, 2 -> g_h2.  Output always g_agg.
__global__ void k_agg(const float* __restrict__ Xin, int srcSel, int n) {
    int w    = (blockIdx.x * blockDim.x + threadIdx.x) >> 5;
    int lane = threadIdx.x & 31;
    if (w >= n) return;
    const float* __restrict__ src = (srcSel == 0) ? Xin : (srcSel == 1 ? g_h1 : g_h2);
    int s = g_off[w], e = g_off[w + 1];
    float ax = 0.f, ay = 0.f;
    int j = s;
    int l2 = lane << 1;
    for (; j + 3 < e; j += 4) {
        int c0 = g_csr[j], c1 = g_csr[j + 1], c2 = g_csr[j + 2], c3 = g_csr[j + 3];
        float2 v0 = *(const float2*)(src + c0 * C + l2);
        float2 v1 = *(const float2*)(src + c1 * C + l2);
        float2 v2 = *(const float2*)(src + c2 * C + l2);
        float2 v3 = *(const float2*)(src + c3 * C + l2);
        ax += (v0.x + v1.x) + (v2.x + v3.x);
        ay += (v0.y + v1.y) + (v2.y + v3.y);
    }
    for (; j < e; j++) {
        int c = g_csr[j];
        float2 v = *(const float2*)(src + c * C + l2);
        ax += v.x; ay += v.y;
    }
    float d = g_dinv[w];
    *(float2*)(g_agg + w * C + l2) = make_float2(ax * d, ay * d);
}

// ---------------- GEMM: OUT[n,64] = act( concat(X, AGG)[n,128] @ W^T + b ) --
// Block tile: 128 nodes x 64 cols, k chunked by 32. Thread tile 8x4.
#define NT  128
#define KC  32
#define NTP 132   // padded (16B-multiple rows -> LDS.128 aligned)
#define WTP 68

__global__ __launch_bounds__(256) void k_gemm(
    const float* __restrict__ Xin, int srcSel,
    const float* __restrict__ W, const float* __restrict__ B,
    int dstSel, int n, int do_relu)
{
    __shared__ float Hs[KC][NTP];
    __shared__ float Ws[KC][WTP];

    const float* __restrict__ Xs = (srcSel == 0) ? Xin : (srcSel == 1 ? g_h1 : g_h2);
    float* __restrict__ OUT = (dstSel == 1) ? g_h1 : g_h2;

    int t  = threadIdx.x;
    int nb = blockIdx.x * NT;
    int tx = t & 15;      // node-group (16 groups x 8 nodes)
    int ty = t >> 4;      // col-group  (16 groups x 4 cols)

    float acc[8][4];
    #pragma unroll
    for (int i = 0; i < 8; i++)
        #pragma unroll
        for (int j = 0; j < 4; j++) acc[i][j] = 0.f;

    int nl    = t >> 1;          // local node for H staging (2 threads/row)
    int half  = t & 1;
    int nglob = nb + nl;
    int colw  = t >> 2;          // W staging: col, quarter
    int q     = t & 3;

    for (int c = 0; c < 4; c++) {
        const float* src = (c < 2) ? Xs : g_agg;
        int koff = (c & 1) * 32;     // column offset within the 64-wide source
        int kb   = c * 32;           // global k base (for W)

        // stage H chunk transposed: Hs[kk][node]
        #pragma unroll
        for (int i = 0; i < 4; i++) {
            float4 v = make_float4(0.f, 0.f, 0.f, 0.f);
            if (nglob < n)
                v = *(const float4*)(src + nglob * C + koff + half * 16 + i * 4);
            int kk = half * 16 + i * 4;
            Hs[kk + 0][nl] = v.x;
            Hs[kk + 1][nl] = v.y;
            Hs[kk + 2][nl] = v.z;
            Hs[kk + 3][nl] = v.w;
        }
        // stage W chunk transposed: Ws[kk][col] = W[col][kb+kk]
        #pragma unroll
        for (int i = 0; i < 2; i++) {
            float4 wv = *(const float4*)(W + colw * 128 + kb + q * 8 + i * 4);
            int kk = q * 8 + i * 4;
            Ws[kk + 0][colw] = wv.x;
            Ws[kk + 1][colw] = wv.y;
            Ws[kk + 2][colw] = wv.z;
            Ws[kk + 3][colw] = wv.w;
        }
        __syncthreads();

        #pragma unroll 4
        for (int kk = 0; kk < KC; kk++) {
            float4 a0 = *(const float4*)&Hs[kk][tx * 8];
            float4 a1 = *(const float4*)&Hs[kk][tx * 8 + 4];
            float4 bv = *(const float4*)&Ws[kk][ty * 4];
            float a[8] = {a0.x, a0.y, a0.z, a0.w, a1.x, a1.y, a1.z, a1.w};
            float bb[4] = {bv.x, bv.y, bv.z, bv.w};
            #pragma unroll
            for (int i = 0; i < 8; i++)
                #pragma unroll
                for (int j = 0; j < 4; j++)
                    acc[i][j] += a[i] * bb[j];
        }
        __syncthreads();
    }

    float4 bv = *(const float4*)(B + ty * 4);
    #pragma unroll
    for (int i = 0; i < 8; i++) {
        int ng = nb + tx * 8 + i;
        if (ng < n) {
            float4 o;
            o.x = acc[i][0] + bv.x;
            o.y = acc[i][1] + bv.y;
            o.z = acc[i][2] + bv.z;
            o.w = acc[i][3] + bv.w;
            if (do_relu) {
                o.x = fmaxf(o.x, 0.f); o.y = fmaxf(o.y, 0.f);
                o.z = fmaxf(o.z, 0.f); o.w = fmaxf(o.w, 0.f);
            }
            *(float4*)(OUT + ng * C + ty * 4) = o;
        }
    }
}

// ---------------- layer 3: fused gather + 128-dot + warp reduce -------------
__global__ void k_layer3(const float* __restrict__ W3, const float* __restrict__ B3,
                         float* __restrict__ OUT, int n)
{
    int w    = (blockIdx.x * blockDim.x + threadIdx.x) >> 5;
    int lane = threadIdx.x & 31;
    if (w >= n) return;
    const float* __restrict__ H = g_h2;
    int s = g_off[w], e = g_off[w + 1];
    int l2 = lane << 1;
    float ax = 0.f, ay = 0.f;
    int j = s;
    for (; j + 3 < e; j += 4) {
        int c0 = g_csr[j], c1 = g_csr[j + 1], c2 = g_csr[j + 2], c3 = g_csr[j + 3];
        float2 v0 = *(const float2*)(H + c0 * C + l2);
        float2 v1 = *(const float2*)(H + c1 * C + l2);
        float2 v2 = *(const float2*)(H + c2 * C + l2);
        float2 v3 = *(const float2*)(H + c3 * C + l2);
        ax += (v0.x + v1.x) + (v2.x + v3.x);
        ay += (v0.y + v1.y) + (v2.y + v3.y);
    }
    for (; j < e; j++) {
        int c = g_csr[j];
        float2 v = *(const float2*)(H + c * C + l2);
        ax += v.x; ay += v.y;
    }
    float d = g_dinv[w];
    ax *= d; ay *= d;
    float2 self = *(const float2*)(H + w * C + l2);
    float2 ws   = *(const float2*)(W3 + l2);
    float2 wa   = *(const float2*)(W3 + 64 + l2);
    float p = self.x * ws.x + self.y * ws.y + ax * wa.x + ay * wa.y;
    #pragma unroll
    for (int o = 16; o; o >>= 1) p += __shfl_xor_sync(0xffffffffu, p, o);
    if (lane == 0) OUT[w] = p + B3[0];
}

// ---------------- driver ----------------------------------------------------
extern "C" void kernel_launch(void* const* d_in, const int* in_sizes, int n_in,
                              void* d_out, int out_size)
{
    const float* x  = (const float*)d_in[0];
    const int*   ei = (const int*)  d_in[1];
    const float* W1 = (const float*)d_in[2];
    const float* b1 = (const float*)d_in[3];
    const float* W2 = (const float*)d_in[4];
    const float* b2 = (const float*)d_in[5];
    const float* W3 = (const float*)d_in[6];
    const float* b3 = (const float*)d_in[7];
    float* out = (float*)d_out;

    int n = in_sizes[0] / C;     // 100000
    int e = in_sizes[1] / 2;     // 1600000
    const int* row = ei;
    const int* col = ei + e;

    int nblk = (n + 1023) / 1024;

    // CSR build (reused for all 3 layers)
    k_zero <<<(n + 255) / 256, 256>>>(n);
    k_hist <<<(e + 255) / 256, 256>>>(row, e);
    k_scan1<<<nblk, 1024>>>(n);
    k_scan2<<<1, 1>>>(nblk);
    k_scan3<<<(n + 255) / 256, 256>>>(n, e);
    k_fill <<<(e + 255) / 256, 256>>>(row, col, e);

    int aggBlocks  = (n * 32 + 255) / 256;  // 1 warp per node
    int gemmBlocks = (n + NT - 1) / NT;

    // layer 1: x -> h1
    k_agg <<<aggBlocks, 256>>>(x, 0, n);
    k_gemm<<<gemmBlocks, 256>>>(x, 0, W1, b1, /*dst=*/1, n, /*relu=*/1);
    // layer 2: h1 -> h2
    k_agg <<<aggBlocks, 256>>>(nullptr, 1, n);
    k_gemm<<<gemmBlocks, 256>>>(nullptr, 1, W2, b2, /*dst=*/2, n, /*relu=*/1);
    // layer 3: h2 -> out (fused)
    k_layer3<<<aggBlocks, 256>>>(W3, b3, out, n);
}

// round 5
// speedup vs baseline: 1.1437x; 1.1427x over previous
#include <cuda_runtime.h>

#define MAXN 100000
#define MAXE 1600000
#define C 64

// ---------------- scratch (static device globals; no allocation) ------------
__device__ int   g_count[MAXN];
__device__ int   g_incl[MAXN + 1024];
__device__ int   g_bsum[128];
__device__ int   g_bpref[128];
__device__ int   g_off[MAXN + 1];
__device__ int   g_cur[MAXN];
__device__ int   g_csr[MAXE];
__device__ float g_dinv[MAXN];
__device__ float g_agg[MAXN * C];   // also reused: g_p = g_agg, g_s = g_agg+MAXN
__device__ float g_h1[MAXN * C];
__device__ float g_h2[MAXN * C];

// ---------------- packed f32x2 helpers --------------------------------------
#define FMA2(d, a, b) \
    asm("fma.rn.f32x2 %0, %1, %2, %0;" : "+l"(d) : "l"(a), "l"(b))
#define UNPACK2(lo, hi, v) \
    asm("mov.b64 {%0, %1}, %2;" : "=f"(lo), "=f"(hi) : "l"(v))

// ---------------- CSR build -------------------------------------------------
__global__ void k_zero(int n) {
    int i = blockIdx.x * blockDim.x + threadIdx.x;
    if (i < n) g_count[i] = 0;
}

__global__ void k_hist(const int* __restrict__ row, int e) {
    int i = blockIdx.x * blockDim.x + threadIdx.x;
    if (i < e) atomicAdd(&g_count[row[i]], 1);
}

// block-level inclusive scan (1024 elems/block)
__global__ void k_scan1(int n) {
    __shared__ int sh[1024];
    int t = threadIdx.x;
    int i = blockIdx.x * 1024 + t;
    sh[t] = (i < n) ? g_count[i] : 0;
    __syncthreads();
    #pragma unroll
    for (int off = 1; off < 1024; off <<= 1) {
        int add = (t >= off) ? sh[t - off] : 0;
        __syncthreads();
        sh[t] += add;
        __syncthreads();
    }
    g_incl[i] = sh[t];
    if (t == 1023) g_bsum[blockIdx.x] = sh[1023];
}

// parallel exclusive scan of the <=128 block sums (single block, 128 threads)
__global__ void k_scan2(int nblk) {
    __shared__ int sh[128];
    int t = threadIdx.x;
    sh[t] = (t < nblk) ? g_bsum[t] : 0;
    __syncthreads();
    #pragma unroll
    for (int off = 1; off < 128; off <<= 1) {
        int add = (t >= off) ? sh[t - off] : 0;
        __syncthreads();
        sh[t] += add;
        __syncthreads();
    }
    int incl = sh[t];
    int v = (t < nblk) ? g_bsum[t] : 0;
    if (t < nblk) g_bpref[t] = incl - v;   // exclusive prefix
}

__global__ void k_scan3(int n, int e) {
    int i = blockIdx.x * blockDim.x + threadIdx.x;
    if (i < n) {
        int cnt = g_count[i];
        int off = g_incl[i] - cnt + g_bpref[i >> 10];
        g_off[i]  = off;
        g_cur[i]  = off;
        g_dinv[i] = 1.0f / (float)(cnt > 1 ? cnt : 1);
    }
    if (i == 0) g_off[n] = e;
}

__global__ void k_fill(const int* __restrict__ row, const int* __restrict__ col, int e) {
    int i = blockIdx.x * blockDim.x + threadIdx.x;
    if (i < e) {
        int p = atomicAdd(&g_cur[row[i]], 1);
        g_csr[p] = col[i];
    }
}

// ---------------- mean aggregation: one warp per destination node -----------
// srcSel: 0 -> external X, 1 -> g_h1.  Output always g_agg.
__global__ void k_agg(const float* __restrict__ Xin, int srcSel, int n) {
    int w    = (blockIdx.x * blockDim.x + threadIdx.x) >> 5;
    int lane = threadIdx.x & 31;
    if (w >= n) return;
    const float* __restrict__ src = (srcSel == 0) ? Xin : g_h1;
    int s = g_off[w], e = g_off[w + 1];
    float ax = 0.f, ay = 0.f;
    int j = s;
    int l2 = lane << 1;
    for (; j + 3 < e; j += 4) {
        int c0 = g_csr[j], c1 = g_csr[j + 1], c2 = g_csr[j + 2], c3 = g_csr[j + 3];
        float2 v0 = *(const float2*)(src + c0 * C + l2);
        float2 v1 = *(const float2*)(src + c1 * C + l2);
        float2 v2 = *(const float2*)(src + c2 * C + l2);
        float2 v3 = *(const float2*)(src + c3 * C + l2);
        ax += (v0.x + v1.x) + (v2.x + v3.x);
        ay += (v0.y + v1.y) + (v2.y + v3.y);
    }
    for (; j < e; j++) {
        int c = g_csr[j];
        float2 v = *(const float2*)(src + c * C + l2);
        ax += v.x; ay += v.y;
    }
    float d = g_dinv[w];
    *(float2*)(g_agg + w * C + l2) = make_float2(ax * d, ay * d);
}

// ---------------- GEMM: OUT[n,64] = relu( concat(X, AGG)[n,128] @ W^T + b ) -
// Block tile: 256 nodes x 64 cols, k chunked by 32. Thread tile 8x8 via
// packed f32x2 FFMA: A pairs are adjacent nodes (free from LDS.128 halves),
// B is stored DUPLICATED in smem so a broadcast LDS.128 yields {b,b} pairs.
#define NT2 256
#define KC  32

__global__ __launch_bounds__(256) void k_gemm(
    const float* __restrict__ Xin, int srcSel,
    const float* __restrict__ W, const float* __restrict__ B,
    int dstSel, int n, int do_relu)
{
    __shared__ float Hs[KC][NT2];      // transposed H chunk: Hs[kk][node]
    __shared__ float Wd[KC][128];      // duplicated W chunk: Wd[kk][2c]=Wd[kk][2c+1]=W[c][kb+kk]

    const float* __restrict__ Xs = (srcSel == 0) ? Xin : g_h1;
    float* __restrict__ OUT = (dstSel == 1) ? g_h1 : g_h2;

    int t  = threadIdx.x;
    int nb = blockIdx.x * NT2;
    int tx = t & 31;      // node-group: 32 groups x 8 nodes
    int ty = t >> 5;      // col-group:   8 groups x 8 cols

    // acc[i2][j] = { out[node 2*i2][col j], out[node 2*i2+1][col j] }
    unsigned long long acc[4][8];
    #pragma unroll
    for (int i = 0; i < 4; i++)
        #pragma unroll
        for (int j = 0; j < 8; j++) acc[i][j] = 0ull;

    int nglob = nb + t;          // H staging: one node per thread
    int colw  = t >> 2;          // W staging: col 0..63
    int q     = t & 3;

    for (int c = 0; c < 4; c++) {
        const float* src = (c < 2) ? Xs : g_agg;
        int koff = (c & 1) * 32;     // column offset within the 64-wide source
        int kb   = c * 32;           // global k base (for W)

        // stage H chunk transposed: each thread loads 32 floats of one node row
        const float4* srow = (const float4*)(src + (size_t)nglob * C + koff);
        #pragma unroll
        for (int i = 0; i < 8; i++) {
            float4 v = make_float4(0.f, 0.f, 0.f, 0.f);
            if (nglob < n) v = srow[i];
            int kk = i * 4;
            Hs[kk + 0][t] = v.x;
            Hs[kk + 1][t] = v.y;
            Hs[kk + 2][t] = v.z;
            Hs[kk + 3][t] = v.w;
        }
        // stage W chunk transposed + duplicated
        #pragma unroll
        for (int i = 0; i < 2; i++) {
            int kk = q * 8 + i * 4;
            float4 wv = *(const float4*)(W + colw * 128 + kb + kk);
            Wd[kk + 0][2 * colw] = wv.x;  Wd[kk + 0][2 * colw + 1] = wv.x;
            Wd[kk + 1][2 * colw] = wv.y;  Wd[kk + 1][2 * colw + 1] = wv.y;
            Wd[kk + 2][2 * colw] = wv.z;  Wd[kk + 2][2 * colw + 1] = wv.z;
            Wd[kk + 3][2 * colw] = wv.w;  Wd[kk + 3][2 * colw + 1] = wv.w;
        }
        __syncthreads();

        #pragma unroll 8
        for (int kk = 0; kk < KC; kk++) {
            ulonglong2 aA = *(const ulonglong2*)&Hs[kk][tx * 8];       // {n0n1},{n2n3}
            ulonglong2 aB = *(const ulonglong2*)&Hs[kk][tx * 8 + 4];   // {n4n5},{n6n7}
            const ulonglong2* bp = (const ulonglong2*)&Wd[kk][ty * 16];
            ulonglong2 b01 = bp[0], b23 = bp[1], b45 = bp[2], b67 = bp[3];
            unsigned long long bb[8] = {b01.x, b01.y, b23.x, b23.y,
                                        b45.x, b45.y, b67.x, b67.y};
            #pragma unroll
            for (int j = 0; j < 8; j++) {
                FMA2(acc[0][j], aA.x, bb[j]);
                FMA2(acc[1][j], aA.y, bb[j]);
                FMA2(acc[2][j], aB.x, bb[j]);
                FMA2(acc[3][j], aB.y, bb[j]);
            }
        }
        __syncthreads();
    }

    float4 bb0 = *(const float4*)(B + ty * 8);
    float4 bb1 = *(const float4*)(B + ty * 8 + 4);
    float bias[8] = {bb0.x, bb0.y, bb0.z, bb0.w, bb1.x, bb1.y, bb1.z, bb1.w};

    #pragma unroll
    for (int i2 = 0; i2 < 4; i2++) {
        float lo[8], hi[8];
        #pragma unroll
        for (int j = 0; j < 8; j++) {
            UNPACK2(lo[j], hi[j], acc[i2][j]);
            lo[j] += bias[j]; hi[j] += bias[j];
            if (do_relu) { lo[j] = fmaxf(lo[j], 0.f); hi[j] = fmaxf(hi[j], 0.f); }
        }
        int n0 = nb + tx * 8 + i2 * 2;
        if (n0 < n) {
            float4* o = (float4*)(OUT + (size_t)n0 * C + ty * 8);
            o[0] = make_float4(lo[0], lo[1], lo[2], lo[3]);
            o[1] = make_float4(lo[4], lo[5], lo[6], lo[7]);
        }
        if (n0 + 1 < n) {
            float4* o = (float4*)(OUT + (size_t)(n0 + 1) * C + ty * 8);
            o[0] = make_float4(hi[0], hi[1], hi[2], hi[3]);
            o[1] = make_float4(hi[4], hi[5], hi[6], hi[7]);
        }
    }
}

// ---------------- layer 3 via linearity: agg(h2)@w = agg(h2@w) --------------
// Project each node to two scalars: s = h2·W3[:64] + b3, p = h2·W3[64:].
// One warp per node.
__global__ void k_proj(const float* __restrict__ W3, const float* __restrict__ B3, int n) {
    int w    = (blockIdx.x * blockDim.x + threadIdx.x) >> 5;
    int lane = threadIdx.x & 31;
    if (w >= n) return;
    int l2 = lane << 1;
    float2 v  = *(const float2*)(g_h2 + (size_t)w * C + l2);
    float2 ws = *(const float2*)(W3 + l2);
    float2 wa = *(const float2*)(W3 + 64 + l2);
    float s = v.x * ws.x + v.y * ws.y;
    float p = v.x * wa.x + v.y * wa.y;
    #pragma unroll
    for (int o = 16; o; o >>= 1) {
        s += __shfl_xor_sync(0xffffffffu, s, o);
        p += __shfl_xor_sync(0xffffffffu, p, o);
    }
    if (lane == 0) {
        g_agg[MAXN + w] = s + B3[0];   // g_s
        g_agg[w]        = p;           // g_p
    }
}

// scalar aggregation + combine: out[i] = s[i] + dinv[i] * sum p[neighbors]
__global__ void k_out(float* __restrict__ OUT, int n) {
    int i = blockIdx.x * blockDim.x + threadIdx.x;
    if (i >= n) return;
    int s = g_off[i], e = g_off[i + 1];
    float acc = 0.f;
    for (int j = s; j < e; j++) acc += g_agg[g_csr[j]];   // g_p
    OUT[i] = g_agg[MAXN + i] + acc * g_dinv[i];
}

// ---------------- driver ----------------------------------------------------
extern "C" void kernel_launch(void* const* d_in, const int* in_sizes, int n_in,
                              void* d_out, int out_size)
{
    const float* x  = (const float*)d_in[0];
    const int*   ei = (const int*)  d_in[1];
    const float* W1 = (const float*)d_in[2];
    const float* b1 = (const float*)d_in[3];
    const float* W2 = (const float*)d_in[4];
    const float* b2 = (const float*)d_in[5];
    const float* W3 = (const float*)d_in[6];
    const float* b3 = (const float*)d_in[7];
    float* out = (float*)d_out;

    int n = in_sizes[0] / C;     // 100000
    int e = in_sizes[1] / 2;     // 1600000
    const int* row = ei;
    const int* col = ei + e;

    int nblk = (n + 1023) / 1024;

    // CSR build (reused for all 3 layers)
    k_zero <<<(n + 255) / 256, 256>>>(n);
    k_hist <<<(e + 255) / 256, 256>>>(row, e);
    k_scan1<<<nblk, 1024>>>(n);
    k_scan2<<<1, 128>>>(nblk);
    k_scan3<<<(n + 255) / 256, 256>>>(n, e);
    k_fill <<<(e + 255) / 256, 256>>>(row, col, e);

    int aggBlocks  = (n * 32 + 255) / 256;   // 1 warp per node
    int gemmBlocks = (n + NT2 - 1) / NT2;
    int tpnBlocks  = (n + 255) / 256;        // 1 thread per node

    // layer 1: x -> h1
    k_agg <<<aggBlocks, 256>>>(x, 0, n);
    k_gemm<<<gemmBlocks, 256>>>(x, 0, W1, b1, /*dst=*/1, n, /*relu=*/1);
    // layer 2: h1 -> h2
    k_agg <<<aggBlocks, 256>>>(nullptr, 1, n);
    k_gemm<<<gemmBlocks, 256>>>(nullptr, 1, W2, b2, /*dst=*/2, n, /*relu=*/1);
    // layer 3 (projected scalars -> scalar aggregation)
    k_proj<<<aggBlocks, 256>>>(W3, b3, n);
    k_out <<<tpnBlocks, 256>>>(out, n);
}